// round 10
// baseline (speedup 1.0000x reference)
#include <cuda_runtime.h>
#include <cstdint>

// MobiusFlow4ND — 4 pairs per warp (8 lanes per pair), 21 warps per block.
// Block = 84 pairs = 4 batch rows; grid = B/4 = 1024.
//
// R7 = R6 (two-phase staging, 45KB smem, 3 blocks/SM = 63 warps) with the
// staging address arithmetic hoisted out:
//   chunk i of a lane always serves pair i at dst0 + i*544 / src0 + i*1024,
//   dst0 = sbase + wid*4*544 + lane*16,
//   src0 = warpSrc + lane*16 + (lane<8 ? 0 : 128),
//   phase 1 = src0 += (lane<8 ? 128 : 384).
// Staging: 4 cp.async + commit per phase (~6 issues) vs R6's ~80.

#define NPER 21
#define PAIRS_PER_BLOCK 84      // 21 warps * 4 groups
#define ROWS_PER_BLOCK 4
#define ROWF 136                // floats per pair-phase row (544 B; stride mod 32 = 8)
#define SMEM_FLOATS (PAIRS_PER_BLOCK * ROWF)
#define TWO_PI 6.28318530717958647692f
#define PI_F   3.14159265358979323846f
#define HALF_PI 1.57079632679489661923f

__device__ __forceinline__ void cp16(uint32_t dst, const char* src) {
    asm volatile("cp.async.cg.shared.global [%0], [%1], 16;" :: "r"(dst), "l"(src));
}

__device__ __forceinline__ float fast_atan2f(float y, float x) {
    float ax = fabsf(x), ay = fabsf(y);
    float hi = fmaxf(ax, ay);
    float lo = fminf(ax, ay);
    float a  = (hi > 0.0f) ? __fdividef(lo, hi) : 0.0f;
    float s  = a * a;
    // minimax atan on [0,1], max err ~1e-5 rad
    float p = 0.0208351f;
    p = fmaf(p, s, -0.0851330f);
    p = fmaf(p, s,  0.1801410f);
    p = fmaf(p, s, -0.3302995f);
    p = fmaf(p, s,  0.9998660f);
    p = p * a;
    if (ay > ax)  p = HALF_PI - p;
    if (x < 0.0f) p = PI_F - p;
    return copysignf(p, y);
}

__device__ __forceinline__ float softplus_f(float t) {
    return (t > 15.0f) ? t : __logf(1.0f + __expf(t));
}

// permute arrives either as 3 x int32 or 3 x int64 (little-endian words).
__device__ __forceinline__ void decode_perm(const int* pi, int& p0, int& p1, int& p2) {
    int a = pi[0], b = pi[1], c = pi[2];
    bool is32 = (a >= 0 && a < 3) && (b >= 0 && b < 3) && (c >= 0 && c < 3) &&
                (a != b) && (b != c) && (a != c);
    if (is32) { p0 = a; p1 = b; p2 = c; }
    else      { p0 = pi[0]; p1 = pi[2]; p2 = pi[4]; }
}

__global__ __launch_bounds__(672, 3)
void mobius_kernel(const float* __restrict__ rot,
                   const float* __restrict__ cond,
                   const int* __restrict__ perm,
                   float* __restrict__ out,
                   long long ldj_off,
                   long long npairs,
                   int B)
{
    __shared__ float srow[SMEM_FLOATS];
    __shared__ float sldj[PAIRS_PER_BLOCK];

    const int tid  = threadIdx.x;
    const int lane = tid & 31;
    const int wid  = tid >> 5;           // warp 0..20
    const int g    = lane >> 3;          // group within warp: 0..3
    const int gl   = lane & 7;           // lane within group: 0..7
    const int bp   = wid * 4 + g;        // pair index within block: 0..83

    long long pair = (long long)blockIdx.x * PAIRS_PER_BLOCK + bp;
    const bool active = pair < npairs;
    if (!active) pair = 0;               // clamp; stores guarded

    long long warpPair0 = (long long)blockIdx.x * PAIRS_PER_BLOCK + wid * 4;
    if (warpPair0 > npairs - 4) warpPair0 = npairs - 4;
    const char* warpSrc = (const char*)(cond + warpPair0 * 256);

    // ---- Hoisted staging addresses ----
    // Chunk i of this lane serves pair i: dst0+i*544 (smem), src0+i*1024 (gmem).
    // Lanes 0-7 carry sp chunks; lanes 8-31 carry w chunks (dst off = lane*16
    // in both cases — the layouts line up exactly).
    uint32_t sbase = (uint32_t)__cvta_generic_to_shared(srow);
    const uint32_t dst0 = sbase + (uint32_t)(wid * 4) * 544u + (uint32_t)lane * 16u;
    const char* src0 = warpSrc + lane * 16 + (lane < 8 ? 0 : 128);
    const int dphase = (lane < 8) ? 128 : 384;

    #define STAGE() do {                       \
        cp16(dst0 + 0 * 544, src0 + 0 * 1024); \
        cp16(dst0 + 1 * 544, src0 + 1 * 1024); \
        cp16(dst0 + 2 * 544, src0 + 2 * 1024); \
        cp16(dst0 + 3 * 544, src0 + 3 * 1024); \
        asm volatile("cp.async.commit_group;");\
    } while (0)

    // ---- Stage phase 0, overlap with frame computation ----
    STAGE();

    int p0, p1, p2;
    decode_perm(perm, p0, p1, p2);

    const float* rp = rot + pair * 9;
    float x0 = __ldg(rp + 0 * 3 + p0), x1 = __ldg(rp + 1 * 3 + p0), x2 = __ldg(rp + 2 * 3 + p0);
    float y0 = __ldg(rp + 0 * 3 + p1), y1 = __ldg(rp + 1 * 3 + p1), y2 = __ldg(rp + 2 * 3 + p1);

    float inx = rsqrtf(fmaf(x0, x0, fmaf(x1, x1, x2 * x2)));
    float r0 = -x0 * inx, r1 = -x1 * inx, r2 = -x2 * inx;
    float v0 = fmaf(y1, r2, -y2 * r1);
    float v1 = fmaf(y2, r0, -y0 * r2);
    float v2 = fmaf(y0, r1, -y1 * r0);
    float inv = rsqrtf(fmaf(v0, v0, fmaf(v1, v1, v2 * v2)));
    v0 *= inv; v1 *= inv; v2 *= inv;

    const float* myrow = srow + bp * ROWF;

    float S = 0.0f, A = 0.0f, G = 0.0f;

    #pragma unroll
    for (int phase = 0; phase < 2; ++phase) {
        asm volatile("cp.async.wait_group 0;");
        __syncwarp();

        #pragma unroll
        for (int it = 0; it < 4; ++it) {
            const int kp = gl + it * 8;          // k' within phase

            float sp = softplus_f(myrow[kp]);

            float w0 = myrow[32 + 3 * kp + 0];
            float w1 = myrow[32 + 3 * kp + 1];
            float w2 = myrow[32 + 3 * kp + 2];

            // proj = I - y y^T (raw y)
            float d = fmaf(y0, w0, fmaf(y1, w1, y2 * w2));
            w0 = fmaf(-y0, d, w0);
            w1 = fmaf(-y1, d, w1);
            w2 = fmaf(-y2, d, w2);

            // w *= 0.7/(1+|w|)
            float wn2r = fmaf(w0, w0, fmaf(w1, w1, w2 * w2));
            float wn   = sqrtf(wn2r);
            float sc   = __fdividef(0.7f, 1.0f + wn);
            w0 *= sc; w1 *= sc; w2 *= sc;
            float wn2 = sc * sc * wn2r;

            // zw = x - w ; f = (1-|w|^2)/|zw|^2
            float zw0 = x0 - w0, zw1 = x1 - w1, zw2 = x2 - w2;
            float zn2 = fmaf(zw0, zw0, fmaf(zw1, zw1, zw2 * zw2));
            float f   = __fdividef(1.0f - wn2, zn2);

            // h_z = f*zw - w
            float h0 = fmaf(f, zw0, -w0);
            float h1 = fmaf(f, zw1, -w1);
            float h2 = fmaf(f, zw2, -w2);

            float hv = fmaf(h0, v0, fmaf(h1, v1, h2 * v2));
            float hr = fmaf(h0, r0, fmaf(h1, r1, h2 * r2));

            float rad = fast_atan2f(hv, hr);
            float ang = (rad >= 0.0f) ? rad : rad + TWO_PI;

            S += sp;
            A = fmaf(sp, ang, A);
            G = fmaf(sp, f, G);   // |dh_dtheta| == f (Householder preserves unit norm)
        }

        if (phase == 0) {
            __syncwarp();                        // all lanes done reading phase-0 data
            src0 += dphase;                      // advance to phase-1 source
            STAGE();
        }
    }
    #undef STAGE

    // reduce S, A, G over the 8-lane group
    #pragma unroll
    for (int off = 4; off; off >>= 1) {
        S += __shfl_xor_sync(0xFFFFFFFFu, S, off);
        A += __shfl_xor_sync(0xFFFFFFFFu, A, off);
        G += __shfl_xor_sync(0xFFFFFFFFu, G, off);
    }

    float invS = __fdividef(1.0f, S);
    float ang  = A * invS;
    float sA, cA;
    __sincosf(ang, &sA, &cA);

    float tx0 = fmaf(r0, cA, v0 * sA);
    float tx1 = fmaf(r1, cA, v1 * sA);
    float tx2 = fmaf(r2, cA, v2 * sA);

    float ldj = __logf(G * invS);

    // tz = cross(tx, y) if (p1-p0==1 || p1-p0==-2) else cross(y, tx); normalized
    int dp = p1 - p0;
    bool fwd = (dp == 1) || (dp == -2);
    float a0, a1, a2, b0, b1, b2;
    if (fwd) { a0 = tx0; a1 = tx1; a2 = tx2; b0 = y0;  b1 = y1;  b2 = y2;  }
    else     { a0 = y0;  a1 = y1;  a2 = y2;  b0 = tx0; b1 = tx1; b2 = tx2; }
    float tz0 = fmaf(a1, b2, -a2 * b1);
    float tz1 = fmaf(a2, b0, -a0 * b2);
    float tz2 = fmaf(a0, b1, -a1 * b0);
    float itz = rsqrtf(fmaf(tz0, tz0, fmaf(tz1, tz1, tz2 * tz2)));
    tz0 *= itz; tz1 *= itz; tz2 *= itz;

    // Group leader stores the 3x3 (9 STG issues serve 4 pairs each).
    if (gl == 0 && active) {
        float* op = out + pair * 9;
        op[0 * 3 + p0] = tx0; op[1 * 3 + p0] = tx1; op[2 * 3 + p0] = tx2;
        op[0 * 3 + p1] = y0;  op[1 * 3 + p1] = y1;  op[2 * 3 + p1] = y2;
        op[0 * 3 + p2] = tz0; op[1 * 3 + p2] = tz1; op[2 * 3 + p2] = tz2;
    }

    // Deterministic ldj row-sums: 84 pairs = 4 rows per block.
    if (gl == 0) sldj[bp] = active ? ldj : 0.0f;
    __syncthreads();
    if (tid < ROWS_PER_BLOCK) {
        long long row = (long long)blockIdx.x * ROWS_PER_BLOCK + tid;
        if (row < B) {
            float s = 0.0f;
            #pragma unroll
            for (int i = 0; i < NPER; ++i) s += sldj[tid * NPER + i];
            out[ldj_off + row] = s;
        }
    }
}

extern "C" void kernel_launch(void* const* d_in, const int* in_sizes, int n_in,
                              void* d_out, int out_size) {
    const float* rot  = (const float*)d_in[0];
    const float* cond = (const float*)d_in[1];
    const int*   perm = (const int*)d_in[2];
    float* out = (float*)d_out;

    const long long rot_elems = in_sizes[0];          // B*N*9
    const long long npairs    = rot_elems / 9;        // B*N
    const int B = (int)(npairs / NPER);               // 4096
    const long long ldj_off = rot_elems;              // trotation first, then ldj[B]

    const int grid = (int)((npairs + PAIRS_PER_BLOCK - 1) / PAIRS_PER_BLOCK);
    mobius_kernel<<<grid, 672>>>(rot, cond, perm, out, ldj_off, npairs, B);
}

// round 13
// speedup vs baseline: 1.0770x; 1.0770x over previous
#include <cuda_runtime.h>
#include <cstdint>

// MobiusFlow4ND — 4 pairs per warp (8 lanes per pair), 21 warps per block.
// Block = 84 pairs = 4 batch rows; grid = B/4 = 1024.
//
// R12 = R10 (R5 architecture + 3 instruction cuts) with the cudaFuncSetAttribute
// call guarded to run once, BEFORE graph capture (unguarded mid-capture API call
// is the prime suspect for the R10 container failure; the guarded form is the
// exact pattern that passed in R5/R6).
//
// Instruction cuts vs R5:
//   1. IEEE sqrtf -> wn2r * rsqrtf(wn2r) (guarded)    (~8 instrs -> 3 per k)
//   2. atan2 [0,2pi) mapping folded into quadrant fixups (hv>=0 ? q : 2pi-q)
//   3. fully-hoisted staging addresses (immediate offsets, ~10 issues/warp)

#define NPER 21
#define PAIRS_PER_BLOCK 84      // 21 warps * 4 groups
#define ROWS_PER_BLOCK 4
#define ROW_F 264               // padded row stride in floats (1056 B; mod 32 = 8)
#define SMEM_FLOATS (PAIRS_PER_BLOCK * ROW_F)
#define SMEM_BYTES  (SMEM_FLOATS * 4 + PAIRS_PER_BLOCK * 4)
#define TWO_PI 6.28318530717958647692f
#define PI_F   3.14159265358979323846f
#define HALF_PI 1.57079632679489661923f

__device__ __forceinline__ void cp16(uint32_t dst, const char* src) {
    asm volatile("cp.async.cg.shared.global [%0], [%1], 16;" :: "r"(dst), "l"(src));
}

// Weighted-angle helper: returns atan2(y,x) mapped to [0, 2pi).
// q = |atan2| in [0,pi] via two quadrant fixups; result = y>=0 ? q : 2pi-q.
__device__ __forceinline__ float ang02pi(float y, float x) {
    float ax = fabsf(x), ay = fabsf(y);
    float hi = fmaxf(ax, ay);
    float lo = fminf(ax, ay);
    float a  = (hi > 0.0f) ? __fdividef(lo, hi) : 0.0f;
    float s  = a * a;
    // minimax atan on [0,1], max err ~1e-5 rad
    float p = 0.0208351f;
    p = fmaf(p, s, -0.0851330f);
    p = fmaf(p, s,  0.1801410f);
    p = fmaf(p, s, -0.3302995f);
    p = fmaf(p, s,  0.9998660f);
    p = p * a;
    if (ay > ax)  p = HALF_PI - p;
    if (x < 0.0f) p = PI_F - p;          // now p = q in [0, pi]
    return (y >= 0.0f) ? p : TWO_PI - p;
}

__device__ __forceinline__ float softplus_f(float t) {
    return (t > 15.0f) ? t : __logf(1.0f + __expf(t));
}

// permute arrives either as 3 x int32 or 3 x int64 (little-endian words).
__device__ __forceinline__ void decode_perm(const int* pi, int& p0, int& p1, int& p2) {
    int a = pi[0], b = pi[1], c = pi[2];
    bool is32 = (a >= 0 && a < 3) && (b >= 0 && b < 3) && (c >= 0 && c < 3) &&
                (a != b) && (b != c) && (a != c);
    if (is32) { p0 = a; p1 = b; p2 = c; }
    else      { p0 = pi[0]; p1 = pi[2]; p2 = pi[4]; }
}

__global__ __launch_bounds__(672, 2)
void mobius_kernel(const float* __restrict__ rot,
                   const float* __restrict__ cond,
                   const int* __restrict__ perm,
                   float* __restrict__ out,
                   long long ldj_off,
                   long long npairs,
                   int B)
{
    extern __shared__ float smem[];
    float* sldj = smem + SMEM_FLOATS;

    const int tid  = threadIdx.x;
    const int lane = tid & 31;
    const int wid  = tid >> 5;           // warp 0..20
    const int g    = lane >> 3;          // group within warp: 0..3
    const int gl   = lane & 7;           // lane within group: 0..7
    const int bp   = wid * 4 + g;        // pair index within block: 0..83

    long long pair = (long long)blockIdx.x * PAIRS_PER_BLOCK + bp;
    const bool active = pair < npairs;
    if (!active) pair = 0;               // clamp; stores guarded

    long long warpPair0 = (long long)blockIdx.x * PAIRS_PER_BLOCK + wid * 4;
    if (warpPair0 > npairs - 4) warpPair0 = npairs - 4;
    const char* warpSrc = (const char*)(cond + warpPair0 * 256);

    // ---- Hoisted single-phase staging: this warp's 4 contiguous rows (4KB).
    // Chunk i of this lane: pair (i>>1), 16B slot ((i&1)*32 + lane).
    // All offsets are immediates off (dstB, srcB).
    uint32_t sbase = (uint32_t)__cvta_generic_to_shared(smem);
    const uint32_t dstB = sbase + (uint32_t)(wid * 4) * 1056u + (uint32_t)lane * 16u;
    const char*    srcB = warpSrc + lane * 16;
    cp16(dstB + 0,    srcB + 0);
    cp16(dstB + 512,  srcB + 512);
    cp16(dstB + 1056, srcB + 1024);
    cp16(dstB + 1568, srcB + 1536);
    cp16(dstB + 2112, srcB + 2048);
    cp16(dstB + 2624, srcB + 2560);
    cp16(dstB + 3168, srcB + 3072);
    cp16(dstB + 3680, srcB + 3584);
    asm volatile("cp.async.commit_group;");

    int p0, p1, p2;
    decode_perm(perm, p0, p1, p2);

    // ---- Frame computation overlaps the cp.async flight ----
    const float* rp = rot + pair * 9;
    float x0 = __ldg(rp + 0 * 3 + p0), x1 = __ldg(rp + 1 * 3 + p0), x2 = __ldg(rp + 2 * 3 + p0);
    float y0 = __ldg(rp + 0 * 3 + p1), y1 = __ldg(rp + 1 * 3 + p1), y2 = __ldg(rp + 2 * 3 + p1);

    float inx = rsqrtf(fmaf(x0, x0, fmaf(x1, x1, x2 * x2)));
    float r0 = -x0 * inx, r1 = -x1 * inx, r2 = -x2 * inx;
    float v0 = fmaf(y1, r2, -y2 * r1);
    float v1 = fmaf(y2, r0, -y0 * r2);
    float v2 = fmaf(y0, r1, -y1 * r0);
    float inv = rsqrtf(fmaf(v0, v0, fmaf(v1, v1, v2 * v2)));
    v0 *= inv; v1 *= inv; v2 *= inv;

    asm volatile("cp.async.wait_group 0;");
    __syncwarp();

    const float* myrow = smem + bp * ROW_F;

    float S = 0.0f, A = 0.0f, G = 0.0f;

    #pragma unroll
    for (int it = 0; it < 8; ++it) {
        const int k = gl + it * 8;

        float sp = softplus_f(myrow[k]);

        float w0 = myrow[64 + 3 * k + 0];
        float w1 = myrow[64 + 3 * k + 1];
        float w2 = myrow[64 + 3 * k + 2];

        // proj = I - y y^T (raw y)
        float d = fmaf(y0, w0, fmaf(y1, w1, y2 * w2));
        w0 = fmaf(-y0, d, w0);
        w1 = fmaf(-y1, d, w1);
        w2 = fmaf(-y2, d, w2);

        // w *= 0.7/(1+|w|); |w| via rsqrt (no IEEE-sqrt sequence)
        float wn2r = fmaf(w0, w0, fmaf(w1, w1, w2 * w2));
        float wn   = (wn2r > 0.0f) ? wn2r * rsqrtf(wn2r) : 0.0f;
        float sc   = __fdividef(0.7f, 1.0f + wn);
        w0 *= sc; w1 *= sc; w2 *= sc;
        float wn2 = sc * sc * wn2r;

        // zw = x - w ; f = (1-|w|^2)/|zw|^2
        float zw0 = x0 - w0, zw1 = x1 - w1, zw2 = x2 - w2;
        float zn2 = fmaf(zw0, zw0, fmaf(zw1, zw1, zw2 * zw2));
        float f   = __fdividef(1.0f - wn2, zn2);

        // h_z = f*zw - w
        float h0 = fmaf(f, zw0, -w0);
        float h1 = fmaf(f, zw1, -w1);
        float h2 = fmaf(f, zw2, -w2);

        float hv = fmaf(h0, v0, fmaf(h1, v1, h2 * v2));
        float hr = fmaf(h0, r0, fmaf(h1, r1, h2 * r2));

        float ang = ang02pi(hv, hr);

        S += sp;
        A = fmaf(sp, ang, A);
        G = fmaf(sp, f, G);   // |dh_dtheta| == f (Householder preserves unit norm)
    }

    // reduce S, A, G over the 8-lane group
    #pragma unroll
    for (int off = 4; off; off >>= 1) {
        S += __shfl_xor_sync(0xFFFFFFFFu, S, off);
        A += __shfl_xor_sync(0xFFFFFFFFu, A, off);
        G += __shfl_xor_sync(0xFFFFFFFFu, G, off);
    }

    float invS = __fdividef(1.0f, S);
    float ang  = A * invS;
    float sA, cA;
    __sincosf(ang, &sA, &cA);

    float tx0 = fmaf(r0, cA, v0 * sA);
    float tx1 = fmaf(r1, cA, v1 * sA);
    float tx2 = fmaf(r2, cA, v2 * sA);

    float ldj = __logf(G * invS);

    // tz = cross(tx, y) if (p1-p0==1 || p1-p0==-2) else cross(y, tx); normalized
    int dp = p1 - p0;
    bool fwd = (dp == 1) || (dp == -2);
    float a0, a1, a2, b0, b1, b2;
    if (fwd) { a0 = tx0; a1 = tx1; a2 = tx2; b0 = y0;  b1 = y1;  b2 = y2;  }
    else     { a0 = y0;  a1 = y1;  a2 = y2;  b0 = tx0; b1 = tx1; b2 = tx2; }
    float tz0 = fmaf(a1, b2, -a2 * b1);
    float tz1 = fmaf(a2, b0, -a0 * b2);
    float tz2 = fmaf(a0, b1, -a1 * b0);
    float itz = rsqrtf(fmaf(tz0, tz0, fmaf(tz1, tz1, tz2 * tz2)));
    tz0 *= itz; tz1 *= itz; tz2 *= itz;

    // Group leader stores the 3x3 (9 STG issues serve 4 pairs each).
    if (gl == 0 && active) {
        float* op = out + pair * 9;
        op[0 * 3 + p0] = tx0; op[1 * 3 + p0] = tx1; op[2 * 3 + p0] = tx2;
        op[0 * 3 + p1] = y0;  op[1 * 3 + p1] = y1;  op[2 * 3 + p1] = y2;
        op[0 * 3 + p2] = tz0; op[1 * 3 + p2] = tz1; op[2 * 3 + p2] = tz2;
    }

    // Deterministic ldj row-sums: 84 pairs = 4 rows per block.
    if (gl == 0) sldj[bp] = active ? ldj : 0.0f;
    __syncthreads();
    if (tid < ROWS_PER_BLOCK) {
        long long row = (long long)blockIdx.x * ROWS_PER_BLOCK + tid;
        if (row < B) {
            float s = 0.0f;
            #pragma unroll
            for (int i = 0; i < NPER; ++i) s += sldj[tid * NPER + i];
            out[ldj_off + row] = s;
        }
    }
}

extern "C" void kernel_launch(void* const* d_in, const int* in_sizes, int n_in,
                              void* d_out, int out_size) {
    const float* rot  = (const float*)d_in[0];
    const float* cond = (const float*)d_in[1];
    const int*   perm = (const int*)d_in[2];
    float* out = (float*)d_out;

    const long long rot_elems = in_sizes[0];          // B*N*9
    const long long npairs    = rot_elems / 9;        // B*N
    const int B = (int)(npairs / NPER);               // 4096
    const long long ldj_off = rot_elems;              // trotation first, then ldj[B]

    // One-time, pre-capture (first call is the harness's correctness run).
    // Mid-capture runtime API calls can invalidate graph capture.
    static bool attr_set = false;
    if (!attr_set) {
        cudaFuncSetAttribute(mobius_kernel,
                             cudaFuncAttributeMaxDynamicSharedMemorySize,
                             SMEM_BYTES);
        attr_set = true;
    }

    const int grid = (int)((npairs + PAIRS_PER_BLOCK - 1) / PAIRS_PER_BLOCK);
    mobius_kernel<<<grid, 672, SMEM_BYTES>>>(rot, cond, perm, out, ldj_off, npairs, B);
}

// round 14
// speedup vs baseline: 1.1502x; 1.0679x over previous
#include <cuda_runtime.h>
#include <cstdint>

// MobiusFlow4ND — 4 pairs per warp (8 lanes per pair), 21 warps per block.
// Block = 84 pairs = 4 batch rows; grid = B/4 = 1024.
//
// R13 = R12 (R5 architecture + instruction cuts) + explicit 2-stage software
// pipeline in the k-loop: iteration it+1's LDS operands (sp, w0, w1, w2) are
// prefetched before iteration it's long dependency tail (f/h/atan2), so each
// warp always has a second independent chain in flight. R12 evidence: the loop
// is chain-latency-bound (one ~150-cycle serial chain per iter at regs=40),
// not instruction-count-bound.

#define NPER 21
#define PAIRS_PER_BLOCK 84      // 21 warps * 4 groups
#define ROWS_PER_BLOCK 4
#define ROW_F 264               // padded row stride in floats (1056 B; mod 32 = 8)
#define SMEM_FLOATS (PAIRS_PER_BLOCK * ROW_F)
#define SMEM_BYTES  (SMEM_FLOATS * 4 + PAIRS_PER_BLOCK * 4)
#define TWO_PI 6.28318530717958647692f
#define PI_F   3.14159265358979323846f
#define HALF_PI 1.57079632679489661923f

__device__ __forceinline__ void cp16(uint32_t dst, const char* src) {
    asm volatile("cp.async.cg.shared.global [%0], [%1], 16;" :: "r"(dst), "l"(src));
}

// atan2(y,x) mapped to [0, 2pi): q = |atan2| in [0,pi]; result = y>=0 ? q : 2pi-q.
__device__ __forceinline__ float ang02pi(float y, float x) {
    float ax = fabsf(x), ay = fabsf(y);
    float hi = fmaxf(ax, ay);
    float lo = fminf(ax, ay);
    float a  = (hi > 0.0f) ? __fdividef(lo, hi) : 0.0f;
    float s  = a * a;
    // minimax atan on [0,1], max err ~1e-5 rad
    float p = 0.0208351f;
    p = fmaf(p, s, -0.0851330f);
    p = fmaf(p, s,  0.1801410f);
    p = fmaf(p, s, -0.3302995f);
    p = fmaf(p, s,  0.9998660f);
    p = p * a;
    if (ay > ax)  p = HALF_PI - p;
    if (x < 0.0f) p = PI_F - p;          // now p = q in [0, pi]
    return (y >= 0.0f) ? p : TWO_PI - p;
}

__device__ __forceinline__ float softplus_f(float t) {
    return (t > 15.0f) ? t : __logf(1.0f + __expf(t));
}

// permute arrives either as 3 x int32 or 3 x int64 (little-endian words).
__device__ __forceinline__ void decode_perm(const int* pi, int& p0, int& p1, int& p2) {
    int a = pi[0], b = pi[1], c = pi[2];
    bool is32 = (a >= 0 && a < 3) && (b >= 0 && b < 3) && (c >= 0 && c < 3) &&
                (a != b) && (b != c) && (a != c);
    if (is32) { p0 = a; p1 = b; p2 = c; }
    else      { p0 = pi[0]; p1 = pi[2]; p2 = pi[4]; }
}

__global__ __launch_bounds__(672, 2)
void mobius_kernel(const float* __restrict__ rot,
                   const float* __restrict__ cond,
                   const int* __restrict__ perm,
                   float* __restrict__ out,
                   long long ldj_off,
                   long long npairs,
                   int B)
{
    extern __shared__ float smem[];
    float* sldj = smem + SMEM_FLOATS;

    const int tid  = threadIdx.x;
    const int lane = tid & 31;
    const int wid  = tid >> 5;           // warp 0..20
    const int g    = lane >> 3;          // group within warp: 0..3
    const int gl   = lane & 7;           // lane within group: 0..7
    const int bp   = wid * 4 + g;        // pair index within block: 0..83

    long long pair = (long long)blockIdx.x * PAIRS_PER_BLOCK + bp;
    const bool active = pair < npairs;
    if (!active) pair = 0;               // clamp; stores guarded

    long long warpPair0 = (long long)blockIdx.x * PAIRS_PER_BLOCK + wid * 4;
    if (warpPair0 > npairs - 4) warpPair0 = npairs - 4;
    const char* warpSrc = (const char*)(cond + warpPair0 * 256);

    // ---- Hoisted single-phase staging: this warp's 4 contiguous rows (4KB).
    uint32_t sbase = (uint32_t)__cvta_generic_to_shared(smem);
    const uint32_t dstB = sbase + (uint32_t)(wid * 4) * 1056u + (uint32_t)lane * 16u;
    const char*    srcB = warpSrc + lane * 16;
    cp16(dstB + 0,    srcB + 0);
    cp16(dstB + 512,  srcB + 512);
    cp16(dstB + 1056, srcB + 1024);
    cp16(dstB + 1568, srcB + 1536);
    cp16(dstB + 2112, srcB + 2048);
    cp16(dstB + 2624, srcB + 2560);
    cp16(dstB + 3168, srcB + 3072);
    cp16(dstB + 3680, srcB + 3584);
    asm volatile("cp.async.commit_group;");

    int p0, p1, p2;
    decode_perm(perm, p0, p1, p2);

    // ---- Frame computation overlaps the cp.async flight ----
    const float* rp = rot + pair * 9;
    float x0 = __ldg(rp + 0 * 3 + p0), x1 = __ldg(rp + 1 * 3 + p0), x2 = __ldg(rp + 2 * 3 + p0);
    float y0 = __ldg(rp + 0 * 3 + p1), y1 = __ldg(rp + 1 * 3 + p1), y2 = __ldg(rp + 2 * 3 + p1);

    float inx = rsqrtf(fmaf(x0, x0, fmaf(x1, x1, x2 * x2)));
    float r0 = -x0 * inx, r1 = -x1 * inx, r2 = -x2 * inx;
    float v0 = fmaf(y1, r2, -y2 * r1);
    float v1 = fmaf(y2, r0, -y0 * r2);
    float v2 = fmaf(y0, r1, -y1 * r0);
    float inv = rsqrtf(fmaf(v0, v0, fmaf(v1, v1, v2 * v2)));
    v0 *= inv; v1 *= inv; v2 *= inv;

    asm volatile("cp.async.wait_group 0;");
    __syncwarp();

    const float* myrow = smem + bp * ROW_F;

    float S = 0.0f, A = 0.0f, G = 0.0f;

    // ---- Software-pipelined k-loop: prefetch it+1's operands before it's tail.
    float spRaw = myrow[gl];
    float nw0 = myrow[64 + 3 * gl + 0];
    float nw1 = myrow[64 + 3 * gl + 1];
    float nw2 = myrow[64 + 3 * gl + 2];

    #pragma unroll
    for (int it = 0; it < 8; ++it) {
        // current operands
        float spc = spRaw;
        float w0 = nw0, w1 = nw1, w2 = nw2;

        // softplus head (independent MUFU chain) starts immediately
        float sp = softplus_f(spc);

        // chain head for current iteration
        float d = fmaf(y0, w0, fmaf(y1, w1, y2 * w2));
        w0 = fmaf(-y0, d, w0);
        w1 = fmaf(-y1, d, w1);
        w2 = fmaf(-y2, d, w2);

        float wn2r = fmaf(w0, w0, fmaf(w1, w1, w2 * w2));
        float wn   = (wn2r > 0.0f) ? wn2r * rsqrtf(wn2r) : 0.0f;

        // ---- prefetch next iteration's operands (independent of the tail) ----
        if (it < 7) {
            const int kn = gl + (it + 1) * 8;
            spRaw = myrow[kn];
            nw0 = myrow[64 + 3 * kn + 0];
            nw1 = myrow[64 + 3 * kn + 1];
            nw2 = myrow[64 + 3 * kn + 2];
        }

        // ---- tail of current iteration ----
        float sc = __fdividef(0.7f, 1.0f + wn);
        w0 *= sc; w1 *= sc; w2 *= sc;
        float wn2 = sc * sc * wn2r;

        float zw0 = x0 - w0, zw1 = x1 - w1, zw2 = x2 - w2;
        float zn2 = fmaf(zw0, zw0, fmaf(zw1, zw1, zw2 * zw2));
        float f   = __fdividef(1.0f - wn2, zn2);

        float h0 = fmaf(f, zw0, -w0);
        float h1 = fmaf(f, zw1, -w1);
        float h2 = fmaf(f, zw2, -w2);

        float hv = fmaf(h0, v0, fmaf(h1, v1, h2 * v2));
        float hr = fmaf(h0, r0, fmaf(h1, r1, h2 * r2));

        float ang = ang02pi(hv, hr);

        S += sp;
        A = fmaf(sp, ang, A);
        G = fmaf(sp, f, G);   // |dh_dtheta| == f (Householder preserves unit norm)
    }

    // reduce S, A, G over the 8-lane group
    #pragma unroll
    for (int off = 4; off; off >>= 1) {
        S += __shfl_xor_sync(0xFFFFFFFFu, S, off);
        A += __shfl_xor_sync(0xFFFFFFFFu, A, off);
        G += __shfl_xor_sync(0xFFFFFFFFu, G, off);
    }

    float invS = __fdividef(1.0f, S);
    float ang  = A * invS;
    float sA, cA;
    __sincosf(ang, &sA, &cA);

    float tx0 = fmaf(r0, cA, v0 * sA);
    float tx1 = fmaf(r1, cA, v1 * sA);
    float tx2 = fmaf(r2, cA, v2 * sA);

    float ldj = __logf(G * invS);

    // tz = cross(tx, y) if (p1-p0==1 || p1-p0==-2) else cross(y, tx); normalized
    int dp = p1 - p0;
    bool fwd = (dp == 1) || (dp == -2);
    float a0, a1, a2, b0, b1, b2;
    if (fwd) { a0 = tx0; a1 = tx1; a2 = tx2; b0 = y0;  b1 = y1;  b2 = y2;  }
    else     { a0 = y0;  a1 = y1;  a2 = y2;  b0 = tx0; b1 = tx1; b2 = tx2; }
    float tz0 = fmaf(a1, b2, -a2 * b1);
    float tz1 = fmaf(a2, b0, -a0 * b2);
    float tz2 = fmaf(a0, b1, -a1 * b0);
    float itz = rsqrtf(fmaf(tz0, tz0, fmaf(tz1, tz1, tz2 * tz2)));
    tz0 *= itz; tz1 *= itz; tz2 *= itz;

    // Group leader stores the 3x3 (9 STG issues serve 4 pairs each).
    if (gl == 0 && active) {
        float* op = out + pair * 9;
        op[0 * 3 + p0] = tx0; op[1 * 3 + p0] = tx1; op[2 * 3 + p0] = tx2;
        op[0 * 3 + p1] = y0;  op[1 * 3 + p1] = y1;  op[2 * 3 + p1] = y2;
        op[0 * 3 + p2] = tz0; op[1 * 3 + p2] = tz1; op[2 * 3 + p2] = tz2;
    }

    // Deterministic ldj row-sums: 84 pairs = 4 rows per block.
    if (gl == 0) sldj[bp] = active ? ldj : 0.0f;
    __syncthreads();
    if (tid < ROWS_PER_BLOCK) {
        long long row = (long long)blockIdx.x * ROWS_PER_BLOCK + tid;
        if (row < B) {
            float s = 0.0f;
            #pragma unroll
            for (int i = 0; i < NPER; ++i) s += sldj[tid * NPER + i];
            out[ldj_off + row] = s;
        }
    }
}

extern "C" void kernel_launch(void* const* d_in, const int* in_sizes, int n_in,
                              void* d_out, int out_size) {
    const float* rot  = (const float*)d_in[0];
    const float* cond = (const float*)d_in[1];
    const int*   perm = (const int*)d_in[2];
    float* out = (float*)d_out;

    const long long rot_elems = in_sizes[0];          // B*N*9
    const long long npairs    = rot_elems / 9;        // B*N
    const int B = (int)(npairs / NPER);               // 4096
    const long long ldj_off = rot_elems;              // trotation first, then ldj[B]

    // One-time, pre-capture (first call is the harness's correctness run).
    static bool attr_set = false;
    if (!attr_set) {
        cudaFuncSetAttribute(mobius_kernel,
                             cudaFuncAttributeMaxDynamicSharedMemorySize,
                             SMEM_BYTES);
        attr_set = true;
    }

    const int grid = (int)((npairs + PAIRS_PER_BLOCK - 1) / PAIRS_PER_BLOCK);
    mobius_kernel<<<grid, 672, SMEM_BYTES>>>(rot, cond, perm, out, ldj_off, npairs, B);
}